// round 17
// baseline (speedup 1.0000x reference)
#include <cuda_runtime.h>
#include <cstdint>

// ---------------------------------------------------------------------------
// WfcNN via warp-level tf32 mma.sync. Round 17: fragment-packed smem layouts.
// A (h1), B (W1), B (Wa) stored in MMA-fragment order so every operand fetch
// is a single conflict-free LDS.128. Accumulation order bit-identical to the
// round-16 kernel (rel_err canary: 3.9188e-4).
// ---------------------------------------------------------------------------

#define BN    262144
#define NE    30
#define TILE  128
#define MAXB  (BN / TILE + NE)   // 2078
#define NT    512

typedef unsigned long long u64;
typedef unsigned int       u32;

__device__ int g_eid[BN];
__device__ int g_sorted[BN];
__device__ int g_counts[NE];
__device__ int g_cursor[NE];
__device__ int g_blk_expert[MAXB];
__device__ int g_blk_base[MAXB];
__device__ int g_blk_n[MAXB];

// ---- helpers --------------------------------------------------------------
__device__ __forceinline__ float tanh_fast(float x) {
    float y; asm("tanh.approx.f32 %0, %1;" : "=f"(y) : "f"(x)); return y;
}
__device__ __forceinline__ u32 to_tf32(float f) {
    u32 r; asm("cvt.rna.tf32.f32 %0, %1;" : "=r"(r) : "f"(f)); return r;
}
__device__ __forceinline__ u64 pk(float lo, float hi) {
    u64 r; asm("mov.b64 %0,{%1,%2};" : "=l"(r) : "f"(lo), "f"(hi)); return r;
}
__device__ __forceinline__ void upk(u64 v, float& lo, float& hi) {
    asm("mov.b64 {%0,%1},%2;" : "=f"(lo), "=f"(hi) : "l"(v));
}
__device__ __forceinline__ u64 ffma2(u64 a, u64 b, u64 c) {
    u64 d; asm("fma.rn.f32x2 %0,%1,%2,%3;" : "=l"(d) : "l"(a), "l"(b), "l"(c));
    return d;
}
__device__ __forceinline__ void mma8(float* d, u32 a0, u32 a1, u32 a2, u32 a3,
                                     u32 b0, u32 b1) {
    asm volatile(
        "mma.sync.aligned.m16n8k8.row.col.f32.tf32.tf32.f32 "
        "{%0,%1,%2,%3}, {%4,%5,%6,%7}, {%8,%9}, {%0,%1,%2,%3};"
        : "+f"(d[0]), "+f"(d[1]), "+f"(d[2]), "+f"(d[3])
        : "r"(a0), "r"(a1), "r"(a2), "r"(a3), "r"(b0), "r"(b1));
}

// ---- sort prologue --------------------------------------------------------
__global__ void k_hist(const int* __restrict__ n, const int* __restrict__ l,
                       const int* __restrict__ m) {
    __shared__ int sh[NE];
    int t = threadIdx.x;
    if (t < NE) sh[t] = 0;
    __syncthreads();
    int i  = blockIdx.x * NT + t;
    int nn = n[i], ll = l[i], mm = m[i];
    int off = (nn - 1) * nn * (2 * nn - 1) / 6;
    int eid = off + ll * ll + ll + mm;
    g_eid[i] = eid;
    atomicAdd(&sh[eid], 1);
    __syncthreads();
    if (t < NE && sh[t]) atomicAdd(&g_counts[t], sh[t]);
}

__global__ void k_scan() {
    __shared__ int soff[NE + 1], sblk[NE + 1], scnt[NE];
    int t = threadIdx.x;
    if (t == 0) {
        int off = 0, blk = 0;
        for (int e = 0; e < NE; e++) {
            int c = g_counts[e];
            scnt[e] = c; soff[e] = off; sblk[e] = blk;
            g_cursor[e] = off;
            g_counts[e] = 0;                    // reset for next graph replay
            off += c;
            blk += (c + TILE - 1) / TILE;
        }
        soff[NE] = off; sblk[NE] = blk;
    }
    __syncthreads();
    int total = sblk[NE];
    for (int b = t; b < MAXB; b += blockDim.x) {
        if (b >= total) { g_blk_expert[b] = -1; continue; }
        int e = 0;
        while (!(b >= sblk[e] && b < sblk[e + 1])) e++;
        int j = b - sblk[e];
        g_blk_expert[b] = e;
        g_blk_base[b]   = soff[e] + j * TILE;
        g_blk_n[b]      = min(TILE, scnt[e] - j * TILE);
    }
}

__global__ void k_scatter() {
    __shared__ int scnt[NE], sbase[NE];
    int t = threadIdx.x;
    if (t < NE) scnt[t] = 0;
    __syncthreads();
    int i = blockIdx.x * NT + t;
    int e = g_eid[i];
    int r = atomicAdd(&scnt[e], 1);
    __syncthreads();
    if (t < NE) sbase[t] = scnt[t] ? atomicAdd(&g_cursor[t], scnt[t]) : 0;
    __syncthreads();
    g_sorted[sbase[e] + r] = i;
}

// ---- fused mma main kernel ------------------------------------------------
// smem (floats):
//  sA1  frag h1: 4096 slots x uint4      0   16384
//       (h2 [128][68]=8704 aliases @0; sG [128][33]=4224 @ 8704)
//  sB1  frag W1: 2048 slots x uint4  16384    8192
//  sWA  frag Wa:  512 slots x uint4  24576    2048
//  sx   [128][4]                     26624     512
//  sW0T [128][4]                     27136     512
//  sb1 27648(64) sba 27712(32) sWb 27744(64) sbb 27808(8) sidx 27816(128)
#define OFF_A1   0
#define OFF_H2   0
#define OFF_G    8704
#define OFF_B1   16384
#define OFF_WA   24576
#define OFF_X    26624
#define OFF_W0T  27136
#define OFF_SB1  27648
#define OFF_BA   27712
#define OFF_WB   27744
#define OFF_BB   27808
#define OFF_IDX  27816
#define SMEM_FLOATS 27944
#define SMEM_BYTES  (SMEM_FLOATS * 4)

__global__ __launch_bounds__(NT, 2) void k_main(
    const float* __restrict__ x,
    const float* __restrict__ W0, const float* __restrict__ b0,
    const float* __restrict__ W1, const float* __restrict__ b1,
    const float* __restrict__ Wa, const float* __restrict__ ba,
    const float* __restrict__ Wb, const float* __restrict__ bb,
    float* __restrict__ out)
{
    extern __shared__ float sm[];
    uint4* sA1  = (uint4*)(sm + OFF_A1);    // frag slots: ((m32*16+kk)*2+strip)*32+lane
    u32*   sH2u = (u32*)(sm + OFF_H2);      // h2 [s][f], stride 68 (alias of A1)
    float* sG   = sm + OFF_G;               // g  [s][k], stride 33
    uint4* sB1  = (uint4*)(sm + OFF_B1);    // frag: ((ng*16+kk)*2+krow)*32+lane
    uint4* sWA  = (uint4*)(sm + OFF_WA);    // frag: (kk*2+krow)*32+lane
    float* sx   = sm + OFF_X;
    float* sW0T = sm + OFF_W0T;
    float* sb1  = sm + OFF_SB1;
    float* sba  = sm + OFF_BA;
    float* sWb  = sm + OFF_WB;
    float* sbb  = sm + OFF_BB;
    int*   sidx = (int*)(sm + OFF_IDX);

    const int t = threadIdx.x;
    const int b = blockIdx.x;
    const int e = g_blk_expert[b];
    if (e < 0) return;
    const int base = g_blk_base[b];
    const int nval = g_blk_n[b];

    const int lane = t & 31;
    const int r    = lane >> 2, c = lane & 3;

    // ---- stage weights (fragment order, tf32) + samples ------------------
    {
        // W1 [128k][64n] row-major -> B1 frag slots.
        // slot sid: lane=(r,c); rest: krow=rest&1, kk=(rest>>1)&15, ng=rest>>5
        // value j: W1[kk*8 + c + krow*4][ng*32 + j*8 + r]
#pragma unroll
        for (int i = 0; i < 4; i++) {
            int sid  = t + NT * i;                    // < 2048
            int rest = sid >> 5;
            int krow = rest & 1, kk = (rest >> 1) & 15, ng = rest >> 5;
            int k = kk * 8 + c + krow * 4;
            const float* src = W1 + k * 64 + ng * 32 + r;
            uint4 u = { to_tf32(src[0]),  to_tf32(src[8]),
                        to_tf32(src[16]), to_tf32(src[24]) };
            sB1[sid] = u;
        }
        // Wa[e] [64k][32n] -> WA frag slots (512 slots, 1 per thread)
        {
            int rest = t >> 5;                        // < 16
            int krow = rest & 1, kk = (rest >> 1) & 7;
            int k = kk * 8 + c + krow * 4;
            const float* src = Wa + e * 2048 + k * 32 + r;
            uint4 u = { to_tf32(src[0]),  to_tf32(src[8]),
                        to_tf32(src[16]), to_tf32(src[24]) };
            sWA[t] = u;
        }
        if (t < 128) {
            sW0T[t * 4 + 0] = W0[t];
            sW0T[t * 4 + 1] = W0[128 + t];
            sW0T[t * 4 + 2] = W0[256 + t];
            sW0T[t * 4 + 3] = b0[t];
        }
        if (t < 64) sb1[t] = b1[t];
        if (t < 32) sba[t] = ba[e * 32 + t];
        if (t < 64) sWb[t] = Wb[e * 64 + t];
        if (t < 2)  sbb[t] = bb[e * 2 + t];
        if (t < 128) {
            int pos = base + t;
            if (pos > BN - 1) pos = BN - 1;   // padded tail: compute, no store
            int idx = g_sorted[pos];
            sidx[t] = idx;
            sx[t * 4 + 0] = x[idx * 3 + 0];
            sx[t * 4 + 1] = x[idx * 3 + 1];
            sx[t * 4 + 2] = x[idx * 3 + 2];
            sx[t * 4 + 3] = 1.0f;             // folds b0
        }
    }
    __syncthreads();

    // ---- layer0: h1 = tanh(x@W0+b0) directly into A-fragment slots -------
    // slot sid: lane=(r,c); rest: strip=rest&1, kk=(rest>>1)&15, m32=rest>>5
    // vector = (A[row0][kc], A[row0+8][kc], A[row0][kc+4], A[row0+8][kc+4])
#pragma unroll
    for (int i = 0; i < 8; i++) {
        int sid  = t + NT * i;                        // < 4096
        int rest = sid >> 5;
        int strip = rest & 1, kk = (rest >> 1) & 15, m32 = rest >> 5;
        int row0 = m32 * 32 + strip * 16 + r;
        int kc   = kk * 8 + c;
        float4 x0 = *(const float4*)(sx + row0 * 4);
        float4 x1 = *(const float4*)(sx + (row0 + 8) * 4);
        float4 w0 = *(const float4*)(sW0T + kc * 4);
        float4 w4 = *(const float4*)(sW0T + (kc + 4) * 4);
        float v0 = fmaf(x0.x, w0.x, fmaf(x0.y, w0.y, fmaf(x0.z, w0.z, x0.w * w0.w)));
        float v1 = fmaf(x1.x, w0.x, fmaf(x1.y, w0.y, fmaf(x1.z, w0.z, x1.w * w0.w)));
        float v2 = fmaf(x0.x, w4.x, fmaf(x0.y, w4.y, fmaf(x0.z, w4.z, x0.w * w4.w)));
        float v3 = fmaf(x1.x, w4.x, fmaf(x1.y, w4.y, fmaf(x1.z, w4.z, x1.w * w4.w)));
        uint4 u = { to_tf32(tanh_fast(v0)), to_tf32(tanh_fast(v1)),
                    to_tf32(tanh_fast(v2)), to_tf32(tanh_fast(v3)) };
        sA1[sid] = u;
    }
    __syncthreads();

    const int w = t >> 5;

    // ---- layer1 MMA: 128x64x128, 8 warps, 32m x 32n tiles ----------------
    if (w < 8) {
        const int m32 = w & 3;           // m0 = m32*32
        const int ng  = w >> 2;          // nbase = ng*32
        float acc[2][4][4] = {};
#pragma unroll
        for (int kk = 0; kk < 16; kk++) {
            uint4 bv0 = sB1[((ng  * 16 + kk) * 2 + 0) * 32 + lane];
            uint4 bv1 = sB1[((ng  * 16 + kk) * 2 + 1) * 32 + lane];
            uint4 av0 = sA1[((m32 * 16 + kk) * 2 + 0) * 32 + lane];
            uint4 av1 = sA1[((m32 * 16 + kk) * 2 + 1) * 32 + lane];
            mma8(acc[0][0], av0.x, av0.y, av0.z, av0.w, bv0.x, bv1.x);
            mma8(acc[0][1], av0.x, av0.y, av0.z, av0.w, bv0.y, bv1.y);
            mma8(acc[0][2], av0.x, av0.y, av0.z, av0.w, bv0.z, bv1.z);
            mma8(acc[0][3], av0.x, av0.y, av0.z, av0.w, bv0.w, bv1.w);
            mma8(acc[1][0], av1.x, av1.y, av1.z, av1.w, bv0.x, bv1.x);
            mma8(acc[1][1], av1.x, av1.y, av1.z, av1.w, bv0.y, bv1.y);
            mma8(acc[1][2], av1.x, av1.y, av1.z, av1.w, bv0.z, bv1.z);
            mma8(acc[1][3], av1.x, av1.y, av1.z, av1.w, bv0.w, bv1.w);
        }
        __syncthreads();   // all layer1 reads of sA1 done before h2 overwrite

        // ---- epilogue A: h2 = tanh(D+b1) -> sH2[s][f] stride 68, tf32 ----
        const int m0    = m32 * 32;
        const int nbase = ng * 32;
#pragma unroll
        for (int strip = 0; strip < 2; strip++) {
            const int mr = m0 + strip * 16 + r;
#pragma unroll
            for (int j = 0; j < 4; j++) {
                int col = nbase + j * 8 + 2 * c;
                float b0v = sb1[col], b1v = sb1[col + 1];
                uint2 lo = { to_tf32(tanh_fast(acc[strip][j][0] + b0v)),
                             to_tf32(tanh_fast(acc[strip][j][1] + b1v)) };
                uint2 hi = { to_tf32(tanh_fast(acc[strip][j][2] + b0v)),
                             to_tf32(tanh_fast(acc[strip][j][3] + b1v)) };
                *(uint2*)(sH2u + mr * 68 + col)       = lo;
                *(uint2*)(sH2u + (mr + 8) * 68 + col) = hi;
            }
        }
    } else {
        __syncthreads();   // matching barrier for idle warps
    }
    __syncthreads();

    // ---- layer2 MMA: 128x32x64, 4 warps, 32m x 32n tiles -----------------
    if (w < 4) {
        const int m0 = w * 32;
        float acc2[2][4][4] = {};
        const u32* pA0 = sH2u + (m0 + r) * 68 + c;
        const u32* pA1 = sH2u + (m0 + r + 8) * 68 + c;
        const u32* pA2 = sH2u + (m0 + 16 + r) * 68 + c;
        const u32* pA3 = sH2u + (m0 + 24 + r) * 68 + c;
#pragma unroll
        for (int kk = 0; kk < 8; kk++) {
            const int k0 = kk * 8;
            uint4 bv0 = sWA[(kk * 2 + 0) * 32 + lane];
            uint4 bv1 = sWA[(kk * 2 + 1) * 32 + lane];
            {
                u32 a0 = pA0[k0], a2 = pA0[k0 + 4];
                u32 a1 = pA1[k0], a3 = pA1[k0 + 4];
                mma8(acc2[0][0], a0, a1, a2, a3, bv0.x, bv1.x);
                mma8(acc2[0][1], a0, a1, a2, a3, bv0.y, bv1.y);
                mma8(acc2[0][2], a0, a1, a2, a3, bv0.z, bv1.z);
                mma8(acc2[0][3], a0, a1, a2, a3, bv0.w, bv1.w);
            }
            {
                u32 a0 = pA2[k0], a2 = pA2[k0 + 4];
                u32 a1 = pA3[k0], a3 = pA3[k0 + 4];
                mma8(acc2[1][0], a0, a1, a2, a3, bv0.x, bv1.x);
                mma8(acc2[1][1], a0, a1, a2, a3, bv0.y, bv1.y);
                mma8(acc2[1][2], a0, a1, a2, a3, bv0.z, bv1.z);
                mma8(acc2[1][3], a0, a1, a2, a3, bv0.w, bv1.w);
            }
        }

        // ---- epilogue B: g = tanh(D+ba) -> sG[s][k] stride 33 (fp32) -----
#pragma unroll
        for (int strip = 0; strip < 2; strip++) {
            const int mr = m0 + strip * 16 + r;
#pragma unroll
            for (int j = 0; j < 4; j++) {
                int col = j * 8 + 2 * c;
                float b0v = sba[col], b1v = sba[col + 1];
                sG[mr * 33 + col]           = tanh_fast(acc2[strip][j][0] + b0v);
                sG[mr * 33 + col + 1]       = tanh_fast(acc2[strip][j][1] + b1v);
                sG[(mr + 8) * 33 + col]     = tanh_fast(acc2[strip][j][2] + b0v);
                sG[(mr + 8) * 33 + col + 1] = tanh_fast(acc2[strip][j][3] + b1v);
            }
        }
    }
    __syncthreads();

    // ---- layer3: psi = g@Wb + bb; normalize; scatter out -----------------
    if (t < 128) {
        const u64* wbp = (const u64*)sWb;
        u64 acc3 = pk(sbb[0], sbb[1]);
        const float* gp = sG + t * 33;
#pragma unroll 8
        for (int k = 0; k < 32; k++) {
            float g = gp[k];
            acc3 = ffma2(pk(g, g), wbp[k], acc3);
        }
        float p0, p1; upk(acc3, p0, p1);
        float rn = rsqrtf(p0 * p0 + p1 * p1 + 1e-6f);
        if (t < nval) {
            int idx = sidx[t];
            out[idx * 2 + 0] = p0 * rn;
            out[idx * 2 + 1] = p1 * rn;
        }
    }
}

// ---------------------------------------------------------------------------
extern "C" void kernel_launch(void* const* d_in, const int* in_sizes, int n_in,
                              void* d_out, int out_size) {
    const float* x  = (const float*)d_in[0];
    const int*   n  = (const int*)d_in[1];
    const int*   l  = (const int*)d_in[2];
    const int*   m  = (const int*)d_in[3];
    const float* W0 = (const float*)d_in[4];
    const float* b0 = (const float*)d_in[5];
    const float* W1 = (const float*)d_in[6];
    const float* b1 = (const float*)d_in[7];
    const float* Wa = (const float*)d_in[8];
    const float* ba = (const float*)d_in[9];
    const float* Wb = (const float*)d_in[10];
    const float* bb = (const float*)d_in[11];
    float* out = (float*)d_out;

    cudaFuncSetAttribute(k_main, cudaFuncAttributeMaxDynamicSharedMemorySize,
                         SMEM_BYTES);

    k_hist   <<<BN / NT, NT>>>(n, l, m);
    k_scan   <<<1, 256>>>();
    k_scatter<<<BN / NT, NT>>>();
    k_main   <<<MAXB, NT, SMEM_BYTES>>>(x, W0, b0, W1, b1, Wa, ba, Wb, bb, out);
}